// round 1
// baseline (speedup 1.0000x reference)
#include <cuda_runtime.h>
#include <math.h>

#define NN 100000
#define EE 1600000
#define KE 64
#define INC 128
#define HID 256
#define OC 16

// ---- static device scratch (no runtime allocation allowed) ----
__device__ float  g_Wt[(size_t)NN * KE];   // MLP_W transposed -> [N,64]
__device__ float  g_S [(size_t)NN * KE];   // xA, then S in place
__device__ int    g_deg[NN];
__device__ int    g_ptr[NN + 1];
__device__ int    g_pos[NN];
__device__ int    g_srt[EE];               // edge sources sorted by dest (CSR)
__device__ int    g_bsum[128];
__device__ int    g_boff[128];
__device__ float  g_SS[KE * KE];
__device__ float  g_Wc[OC * INC];          // fin_Wx @ mlpx_W   [16,128]
__device__ float  g_bc[OC];                // fin_Wx @ mlpx_b + fin_b
__device__ double g_cut;
__device__ double g_dt;

// ---------------------------------------------------------------- zero
__global__ void k_zero() {
    int i = blockIdx.x * blockDim.x + threadIdx.x;
    if (i < NN) g_deg[i] = 0;
    if (i < KE * KE) g_SS[i] = 0.f;
    if (i == 0) { g_cut = 0.0; g_dt = 0.0; }
}

// ---------------------------------------------------------------- transpose MLP_W [64,N] -> [N,64]
__global__ void k_transpose(const float* __restrict__ W) {
    __shared__ float tile[32][33];
    int v0 = blockIdx.x * 32, k0 = blockIdx.y * 32;
    int tx = threadIdx.x, ty = threadIdx.y;           // block (32,8)
    #pragma unroll
    for (int r = ty; r < 32; r += 8)
        tile[r][tx] = W[(size_t)(k0 + r) * NN + v0 + tx];
    __syncthreads();
    #pragma unroll
    for (int r = ty; r < 32; r += 8)
        g_Wt[(size_t)(v0 + r) * KE + k0 + tx] = tile[tx][r];
}

// ---------------------------------------------------------------- combined weights
__global__ void k_wcomb(const float* __restrict__ finW, const float* __restrict__ mlpxW,
                        const float* __restrict__ mlpxb, const float* __restrict__ finb) {
    int t = blockIdx.x * blockDim.x + threadIdx.x;
    if (t < OC * INC) {
        int o = t / INC, c = t % INC;
        float s = 0.f;
        for (int h = 0; h < HID; h++) s += finW[o * 320 + h] * mlpxW[h * INC + c];
        g_Wc[o * INC + c] = s;
    }
    if (t < OC) {
        float s = finb[t];
        for (int h = 0; h < HID; h++) s += finW[t * 320 + h] * mlpxb[h];
        g_bc[t] = s;
    }
}

// ---------------------------------------------------------------- degree histogram
__global__ void k_hist(const int* __restrict__ col) {
    int e = blockIdx.x * blockDim.x + threadIdx.x;
    if (e < EE) atomicAdd(&g_deg[col[e]], 1);
}

// ---------------------------------------------------------------- 3-phase exclusive scan (1024 elems/block)
__global__ void k_scan1() {
    __shared__ int sh[256];
    int t = threadIdx.x;
    int base = blockIdx.x * 1024 + t * 4;
    int v0 = (base + 0 < NN) ? g_deg[base + 0] : 0;
    int v1 = (base + 1 < NN) ? g_deg[base + 1] : 0;
    int v2 = (base + 2 < NN) ? g_deg[base + 2] : 0;
    int v3 = (base + 3 < NN) ? g_deg[base + 3] : 0;
    int s = v0 + v1 + v2 + v3;
    sh[t] = s; __syncthreads();
    for (int off = 1; off < 256; off <<= 1) {
        int x = (t >= off) ? sh[t - off] : 0;
        __syncthreads();
        sh[t] += x;
        __syncthreads();
    }
    int run = sh[t] - s;                  // exclusive offset for this thread
    if (t == 255) g_bsum[blockIdx.x] = sh[255];
    if (base + 0 < NN) g_ptr[base + 0] = run; run += v0;
    if (base + 1 < NN) g_ptr[base + 1] = run; run += v1;
    if (base + 2 < NN) g_ptr[base + 2] = run; run += v2;
    if (base + 3 < NN) g_ptr[base + 3] = run;
}

__global__ void k_scan2(int nblk) {
    __shared__ int sh[128];
    int t = threadIdx.x;
    int v = (t < nblk) ? g_bsum[t] : 0;
    sh[t] = v; __syncthreads();
    for (int off = 1; off < 128; off <<= 1) {
        int x = (t >= off) ? sh[t - off] : 0;
        __syncthreads();
        sh[t] += x;
        __syncthreads();
    }
    g_boff[t] = sh[t] - v;
}

__global__ void k_scan3() {
    int i = blockIdx.x * blockDim.x + threadIdx.x;
    if (i < NN) {
        int p = g_ptr[i] + g_boff[i >> 10];
        g_ptr[i] = p;
        g_pos[i] = p;
    }
    if (i == 0) g_ptr[NN] = EE;
}

// ---------------------------------------------------------------- scatter edges into CSR buckets
__global__ void k_scatter(const int* __restrict__ row, const int* __restrict__ col) {
    int e = blockIdx.x * blockDim.x + threadIdx.x;
    if (e < EE) {
        int p = atomicAdd(&g_pos[col[e]], 1);
        g_srt[p] = row[e];
    }
}

// ---------------------------------------------------------------- SpMM1: xA[c] = sum MLP_Wt[src] + bias  (warp/node)
__global__ void __launch_bounds__(256) k_spmm1(const float* __restrict__ bias) {
    int w = (blockIdx.x * blockDim.x + threadIdx.x) >> 5;   // node (grid exact: 100000 warps)
    int l = threadIdx.x & 31;
    int s = g_ptr[w], e = g_ptr[w + 1];
    const float2* F = (const float2*)g_Wt;
    float a0 = 0.f, a1 = 0.f;
    int i = s;
    for (; i + 2 <= e; i += 2) {
        int s0 = __ldg(&g_srt[i]), s1 = __ldg(&g_srt[i + 1]);
        float2 u = __ldg(&F[(size_t)s0 * 32 + l]);
        float2 v = __ldg(&F[(size_t)s1 * 32 + l]);
        a0 += u.x + v.x; a1 += u.y + v.y;
    }
    if (i < e) {
        int s0 = __ldg(&g_srt[i]);
        float2 u = __ldg(&F[(size_t)s0 * 32 + l]);
        a0 += u.x; a1 += u.y;
    }
    float2 b = __ldg(&((const float2*)bias)[l]);
    ((float2*)g_S)[(size_t)w * 32 + l] = make_float2(a0 + b.x, a1 + b.y);
}

// ---------------------------------------------------------------- softmax rows + deg_term  (warp/node)
__global__ void __launch_bounds__(256) k_softmax() {
    __shared__ double sdt[8];
    int w = (blockIdx.x * blockDim.x + threadIdx.x) >> 5;
    int l = threadIdx.x & 31, wl = (threadIdx.x >> 5);
    float2 v = ((float2*)g_S)[(size_t)w * 32 + l];
    float m = fmaxf(v.x, v.y);
    #pragma unroll
    for (int d = 16; d >= 1; d >>= 1) m = fmaxf(m, __shfl_xor_sync(0xffffffffu, m, d));
    float e0 = expf(v.x - m), e1 = expf(v.y - m);
    float sum = e0 + e1;
    #pragma unroll
    for (int d = 16; d >= 1; d >>= 1) sum += __shfl_xor_sync(0xffffffffu, sum, d);
    float inv = 1.f / sum;
    float s0 = e0 * inv, s1 = e1 * inv;
    ((float2*)g_S)[(size_t)w * 32 + l] = make_float2(s0, s1);
    float ssq = s0 * s0 + s1 * s1;
    #pragma unroll
    for (int d = 16; d >= 1; d >>= 1) ssq += __shfl_xor_sync(0xffffffffu, ssq, d);
    if (l == 0) sdt[wl] = (double)(g_ptr[w + 1] - g_ptr[w]) * (double)ssq;
    __syncthreads();
    if (threadIdx.x == 0) {
        double t = 0.0;
        #pragma unroll
        for (int q = 0; q < 8; q++) t += sdt[q];
        atomicAdd(&g_dt, t);
    }
}

// ---------------------------------------------------------------- SpMM2 fused with cut = sum S*(A S)  (warp/node)
__global__ void __launch_bounds__(256) k_spmm2() {
    __shared__ double scut[8];
    int w = (blockIdx.x * blockDim.x + threadIdx.x) >> 5;
    int l = threadIdx.x & 31, wl = (threadIdx.x >> 5);
    int s = g_ptr[w], e = g_ptr[w + 1];
    const float2* F = (const float2*)g_S;
    float a0 = 0.f, a1 = 0.f;
    int i = s;
    for (; i + 2 <= e; i += 2) {
        int s0 = __ldg(&g_srt[i]), s1 = __ldg(&g_srt[i + 1]);
        float2 u = __ldg(&F[(size_t)s0 * 32 + l]);
        float2 v = __ldg(&F[(size_t)s1 * 32 + l]);
        a0 += u.x + v.x; a1 += u.y + v.y;
    }
    if (i < e) {
        int s0 = __ldg(&g_srt[i]);
        float2 u = __ldg(&F[(size_t)s0 * 32 + l]);
        a0 += u.x; a1 += u.y;
    }
    float2 sc = F[(size_t)w * 32 + l];
    float dot = a0 * sc.x + a1 * sc.y;
    #pragma unroll
    for (int d = 16; d >= 1; d >>= 1) dot += __shfl_xor_sync(0xffffffffu, dot, d);
    if (l == 0) scut[wl] = (double)dot;
    __syncthreads();
    if (threadIdx.x == 0) {
        double t = 0.0;
        #pragma unroll
        for (int q = 0; q < 8; q++) t += scut[q];
        atomicAdd(&g_cut, t);
    }
}

// ---------------------------------------------------------------- SS = S^T S  (4x4 register tiles, LDS.128)
__global__ void __launch_bounds__(256) k_SSmat() {
    __shared__ float4 srow[16][16];      // 16 rows x 64 floats
    int t = threadIdx.x;
    int ti = t >> 4, tj = t & 15;
    float acc[4][4] = {};
    int chunk = (NN + gridDim.x - 1) / gridDim.x;
    int r0 = blockIdx.x * chunk;
    int r1 = min(r0 + chunk, NN);
    const float4* S4 = (const float4*)g_S;
    for (int rb = r0; rb < r1; rb += 16) {
        int nr = min(16, r1 - rb);
        if (t < nr * 16) srow[t >> 4][t & 15] = S4[(size_t)(rb + (t >> 4)) * 16 + (t & 15)];
        __syncthreads();
        for (int r = 0; r < nr; r++) {
            float4 a = srow[r][ti];
            float4 b = srow[r][tj];
            acc[0][0] += a.x * b.x; acc[0][1] += a.x * b.y; acc[0][2] += a.x * b.z; acc[0][3] += a.x * b.w;
            acc[1][0] += a.y * b.x; acc[1][1] += a.y * b.y; acc[1][2] += a.y * b.z; acc[1][3] += a.y * b.w;
            acc[2][0] += a.z * b.x; acc[2][1] += a.z * b.y; acc[2][2] += a.z * b.z; acc[2][3] += a.z * b.w;
            acc[3][0] += a.w * b.x; acc[3][1] += a.w * b.y; acc[3][2] += a.w * b.z; acc[3][3] += a.w * b.w;
        }
        __syncthreads();
    }
    #pragma unroll
    for (int p = 0; p < 4; p++)
        #pragma unroll
        for (int q = 0; q < 4; q++)
            atomicAdd(&g_SS[(ti * 4 + p) * KE + tj * 4 + q], acc[p][q]);
}

// ---------------------------------------------------------------- ortho loss + pump loss -> out[last]
__global__ void k_loss(float* __restrict__ out, int idx) {
    __shared__ double sh[256];
    __shared__ double dnrm;
    int t = threadIdx.x;
    double s = 0.0;
    for (int i = t; i < KE * KE; i += 256) { double v = (double)g_SS[i]; s += v * v; }
    sh[t] = s; __syncthreads();
    for (int off = 128; off >= 1; off >>= 1) { if (t < off) sh[t] += sh[t + off]; __syncthreads(); }
    if (t == 0) dnrm = sqrt(sh[0]);
    __syncthreads();
    double s2 = 0.0;
    for (int i = t; i < KE * KE; i += 256) {
        double v = (double)g_SS[i] / dnrm;
        if ((i >> 6) == (i & 63)) v -= 0.125;   // I / sqrt(64)
        s2 += v * v;
    }
    sh[t] = s2; __syncthreads();
    for (int off = 128; off >= 1; off >>= 1) { if (t < off) sh[t] += sh[t + off]; __syncthreads(); }
    if (t == 0) {
        double loss = -(g_cut / g_dt) + sqrt(sh[0]);
        out[idx] = (float)loss;
    }
}

// ---------------------------------------------------------------- final: logits + log_softmax  (thread = (node,out))
__global__ void __launch_bounds__(256) k_final(const float* __restrict__ x,
                                               const float* __restrict__ finW,
                                               float* __restrict__ out) {
    __shared__ float4 Wx[32][16];   // [c4][o] of combined x-weight
    __shared__ float4 Wa[16][16];   // [k4][o] of fin_W S-part
    __shared__ float  bo[16];
    int t = threadIdx.x;
    for (int idx = t; idx < 512; idx += 256) {
        int c4 = idx >> 4, o = idx & 15;
        Wx[c4][o] = ((const float4*)g_Wc)[o * 32 + c4];
    }
    if (t < 256) {
        int k4 = t >> 4, o = t & 15;
        Wa[k4][o] = ((const float4*)finW)[o * 80 + 64 + k4];   // finW[o][256 + 4k4 ..]
    }
    if (t < 16) bo[t] = g_bc[t];
    __syncthreads();

    int n = blockIdx.x * 16 + (t >> 4);
    int o = t & 15;
    const float4* x4 = (const float4*)x;
    const float4* S4 = (const float4*)g_S;
    float acc = bo[o];
    #pragma unroll 8
    for (int c4 = 0; c4 < 32; c4++) {
        float4 xv = x4[(size_t)n * 32 + c4];
        float4 w = Wx[c4][o];
        acc += xv.x * w.x + xv.y * w.y + xv.z * w.z + xv.w * w.w;
    }
    #pragma unroll 8
    for (int k4 = 0; k4 < 16; k4++) {
        float4 sv = S4[(size_t)n * 16 + k4];
        float4 w = Wa[k4][o];
        acc += sv.x * w.x + sv.y * w.y + sv.z * w.z + sv.w * w.w;
    }
    // log_softmax across the 16-lane group
    float m = acc;
    #pragma unroll
    for (int d = 1; d < 16; d <<= 1) m = fmaxf(m, __shfl_xor_sync(0xffffffffu, m, d));
    float ex = expf(acc - m);
    float sum = ex;
    #pragma unroll
    for (int d = 1; d < 16; d <<= 1) sum += __shfl_xor_sync(0xffffffffu, sum, d);
    out[(size_t)n * 16 + o] = acc - m - logf(sum);
}

// ================================================================ launch
extern "C" void kernel_launch(void* const* d_in, const int* in_sizes, int n_in,
                              void* d_out, int out_size) {
    const float* x     = (const float*)d_in[0];
    const int*   ei    = (const int*)  d_in[1];
    const float* MLPW  = (const float*)d_in[2];
    const float* MLPb  = (const float*)d_in[3];
    const float* mlpxW = (const float*)d_in[4];
    const float* mlpxb = (const float*)d_in[5];
    const float* finW  = (const float*)d_in[6];
    const float* finb  = (const float*)d_in[7];
    float* out = (float*)d_out;

    const int* row = ei;
    const int* col = ei + EE;
    const int nblk_scan = (NN + 1023) / 1024;   // 98

    k_zero<<<(NN + 255) / 256, 256>>>();
    k_transpose<<<dim3(NN / 32, KE / 32), dim3(32, 8)>>>(MLPW);
    k_wcomb<<<8, 256>>>(finW, mlpxW, mlpxb, finb);
    k_hist<<<EE / 256, 256>>>(col);
    k_scan1<<<nblk_scan, 256>>>();
    k_scan2<<<1, 128>>>(nblk_scan);
    k_scan3<<<(NN + 255) / 256, 256>>>();
    k_scatter<<<EE / 256, 256>>>(row, col);
    k_spmm1<<<NN / 8, 256>>>(MLPb);      // 8 warps/block, exact
    k_softmax<<<NN / 8, 256>>>();
    k_spmm2<<<NN / 8, 256>>>();
    k_SSmat<<<592, 256>>>();
    k_loss<<<1, 256>>>(out, out_size - 1);
    k_final<<<NN / 16, 256>>>(x, finW, out);
}

// round 2
// speedup vs baseline: 1.0331x; 1.0331x over previous
#include <cuda_runtime.h>
#include <cuda_fp16.h>
#include <math.h>

#define NN 100000
#define EE 1600000
#define KE 64
#define INC 128
#define HID 256
#define OC 16

// ---- static device scratch (no runtime allocation allowed) ----
__device__ __half  g_Wh[(size_t)NN * KE];  // MLP_W transposed, fp16 -> [N,64]
__device__ float   g_S [(size_t)NN * KE];  // S (fp32, post-softmax)
__device__ __half  g_Sh[(size_t)NN * KE];  // S (fp16 copy for SpMM2 gather)
__device__ int     g_deg[NN];
__device__ int     g_ptr[NN + 1];
__device__ int     g_pos[NN];
__device__ int     g_srt[EE];              // edge sources sorted by dest (CSR)
__device__ int     g_bsum[128];
__device__ int     g_boff[128];
__device__ float   g_SS[KE * KE];
__device__ float   g_Wc[OC * INC];         // fin_Wx @ mlpx_W   [16,128]
__device__ float   g_bc[OC];               // fin_Wx @ mlpx_b + fin_b
__device__ double  g_cut;
__device__ double  g_dt;

// ---------------------------------------------------------------- zero
__global__ void k_zero() {
    int i = blockIdx.x * blockDim.x + threadIdx.x;
    if (i < NN) g_deg[i] = 0;
    if (i < KE * KE) g_SS[i] = 0.f;
    if (i == 0) { g_cut = 0.0; g_dt = 0.0; }
}

// ---------------------------------------------------------------- transpose MLP_W [64,N] -> [N,64] fp16
__global__ void k_transpose(const float* __restrict__ W) {
    __shared__ float tile[32][33];
    int v0 = blockIdx.x * 32, k0 = blockIdx.y * 32;
    int tx = threadIdx.x, ty = threadIdx.y;           // block (32,8)
    #pragma unroll
    for (int r = ty; r < 32; r += 8)
        tile[r][tx] = W[(size_t)(k0 + r) * NN + v0 + tx];
    __syncthreads();
    #pragma unroll
    for (int r = ty; r < 32; r += 8)
        g_Wh[(size_t)(v0 + r) * KE + k0 + tx] = __float2half(tile[tx][r]);
}

// ---------------------------------------------------------------- combined weights
__global__ void k_wcomb(const float* __restrict__ finW, const float* __restrict__ mlpxW,
                        const float* __restrict__ mlpxb, const float* __restrict__ finb) {
    int t = blockIdx.x * blockDim.x + threadIdx.x;
    if (t < OC * INC) {
        int o = t / INC, c = t % INC;
        float s = 0.f;
        for (int h = 0; h < HID; h++) s += finW[o * 320 + h] * mlpxW[h * INC + c];
        g_Wc[o * INC + c] = s;
    }
    if (t < OC) {
        float s = finb[t];
        for (int h = 0; h < HID; h++) s += finW[t * 320 + h] * mlpxb[h];
        g_bc[t] = s;
    }
}

// ---------------------------------------------------------------- degree histogram
__global__ void k_hist(const int* __restrict__ col) {
    int e = blockIdx.x * blockDim.x + threadIdx.x;
    if (e < EE) atomicAdd(&g_deg[col[e]], 1);
}

// ---------------------------------------------------------------- 3-phase exclusive scan (1024 elems/block)
__global__ void k_scan1() {
    __shared__ int sh[256];
    int t = threadIdx.x;
    int base = blockIdx.x * 1024 + t * 4;
    int v0 = (base + 0 < NN) ? g_deg[base + 0] : 0;
    int v1 = (base + 1 < NN) ? g_deg[base + 1] : 0;
    int v2 = (base + 2 < NN) ? g_deg[base + 2] : 0;
    int v3 = (base + 3 < NN) ? g_deg[base + 3] : 0;
    int s = v0 + v1 + v2 + v3;
    sh[t] = s; __syncthreads();
    for (int off = 1; off < 256; off <<= 1) {
        int x = (t >= off) ? sh[t - off] : 0;
        __syncthreads();
        sh[t] += x;
        __syncthreads();
    }
    int run = sh[t] - s;
    if (t == 255) g_bsum[blockIdx.x] = sh[255];
    if (base + 0 < NN) g_ptr[base + 0] = run; run += v0;
    if (base + 1 < NN) g_ptr[base + 1] = run; run += v1;
    if (base + 2 < NN) g_ptr[base + 2] = run; run += v2;
    if (base + 3 < NN) g_ptr[base + 3] = run;
}

__global__ void k_scan2(int nblk) {
    __shared__ int sh[128];
    int t = threadIdx.x;
    int v = (t < nblk) ? g_bsum[t] : 0;
    sh[t] = v; __syncthreads();
    for (int off = 1; off < 128; off <<= 1) {
        int x = (t >= off) ? sh[t - off] : 0;
        __syncthreads();
        sh[t] += x;
        __syncthreads();
    }
    g_boff[t] = sh[t] - v;
}

__global__ void k_scan3() {
    int i = blockIdx.x * blockDim.x + threadIdx.x;
    if (i < NN) {
        int p = g_ptr[i] + g_boff[i >> 10];
        g_ptr[i] = p;
        g_pos[i] = p;
    }
    if (i == 0) g_ptr[NN] = EE;
}

// ---------------------------------------------------------------- scatter edges into CSR buckets
__global__ void k_scatter(const int* __restrict__ row, const int* __restrict__ col) {
    int e = blockIdx.x * blockDim.x + threadIdx.x;
    if (e < EE) {
        int p = atomicAdd(&g_pos[col[e]], 1);
        g_srt[p] = row[e];
    }
}

// ---------------------------------------------------------------- SpMM1 + softmax + deg_term (warp/node)
__global__ void __launch_bounds__(256) k_spmm1(const float* __restrict__ bias) {
    __shared__ double sdt[8];
    int w = (blockIdx.x * blockDim.x + threadIdx.x) >> 5;
    int l = threadIdx.x & 31, wl = threadIdx.x >> 5;
    int s = g_ptr[w], e = g_ptr[w + 1];
    const __half2* F = (const __half2*)g_Wh;
    float a0 = 0.f, a1 = 0.f;
    int i = s;
    for (; i + 4 <= e; i += 4) {
        int s0 = __ldg(&g_srt[i]),     s1 = __ldg(&g_srt[i + 1]);
        int s2 = __ldg(&g_srt[i + 2]), s3 = __ldg(&g_srt[i + 3]);
        float2 f0 = __half22float2(__ldg(&F[(size_t)s0 * 32 + l]));
        float2 f1 = __half22float2(__ldg(&F[(size_t)s1 * 32 + l]));
        float2 f2 = __half22float2(__ldg(&F[(size_t)s2 * 32 + l]));
        float2 f3 = __half22float2(__ldg(&F[(size_t)s3 * 32 + l]));
        a0 += (f0.x + f1.x) + (f2.x + f3.x);
        a1 += (f0.y + f1.y) + (f2.y + f3.y);
    }
    for (; i < e; i++) {
        int s0 = __ldg(&g_srt[i]);
        float2 f = __half22float2(__ldg(&F[(size_t)s0 * 32 + l]));
        a0 += f.x; a1 += f.y;
    }
    float2 b = __ldg(&((const float2*)bias)[l]);
    a0 += b.x; a1 += b.y;
    // softmax across the 64-wide row (2 vals/lane)
    float m = fmaxf(a0, a1);
    #pragma unroll
    for (int d = 16; d >= 1; d >>= 1) m = fmaxf(m, __shfl_xor_sync(0xffffffffu, m, d));
    float e0 = expf(a0 - m), e1 = expf(a1 - m);
    float sum = e0 + e1;
    #pragma unroll
    for (int d = 16; d >= 1; d >>= 1) sum += __shfl_xor_sync(0xffffffffu, sum, d);
    float inv = 1.f / sum;
    float s0 = e0 * inv, s1 = e1 * inv;
    ((float2*)g_S)[(size_t)w * 32 + l] = make_float2(s0, s1);
    ((__half2*)g_Sh)[(size_t)w * 32 + l] = __floats2half2_rn(s0, s1);
    // deg_term contribution: deg[w] * sum(S_w^2)
    float ssq = s0 * s0 + s1 * s1;
    #pragma unroll
    for (int d = 16; d >= 1; d >>= 1) ssq += __shfl_xor_sync(0xffffffffu, ssq, d);
    if (l == 0) sdt[wl] = (double)(e - s) * (double)ssq;
    __syncthreads();
    if (threadIdx.x == 0) {
        double t = 0.0;
        #pragma unroll
        for (int q = 0; q < 8; q++) t += sdt[q];
        atomicAdd(&g_dt, t);
    }
}

// ---------------------------------------------------------------- SpMM2 fused with cut = sum S*(A S)
__global__ void __launch_bounds__(256) k_spmm2() {
    __shared__ double scut[8];
    int w = (blockIdx.x * blockDim.x + threadIdx.x) >> 5;
    int l = threadIdx.x & 31, wl = threadIdx.x >> 5;
    int s = g_ptr[w], e = g_ptr[w + 1];
    const __half2* F = (const __half2*)g_Sh;
    float a0 = 0.f, a1 = 0.f;
    int i = s;
    for (; i + 4 <= e; i += 4) {
        int s0 = __ldg(&g_srt[i]),     s1 = __ldg(&g_srt[i + 1]);
        int s2 = __ldg(&g_srt[i + 2]), s3 = __ldg(&g_srt[i + 3]);
        float2 f0 = __half22float2(__ldg(&F[(size_t)s0 * 32 + l]));
        float2 f1 = __half22float2(__ldg(&F[(size_t)s1 * 32 + l]));
        float2 f2 = __half22float2(__ldg(&F[(size_t)s2 * 32 + l]));
        float2 f3 = __half22float2(__ldg(&F[(size_t)s3 * 32 + l]));
        a0 += (f0.x + f1.x) + (f2.x + f3.x);
        a1 += (f0.y + f1.y) + (f2.y + f3.y);
    }
    for (; i < e; i++) {
        int s0 = __ldg(&g_srt[i]);
        float2 f = __half22float2(__ldg(&F[(size_t)s0 * 32 + l]));
        a0 += f.x; a1 += f.y;
    }
    float2 sc = ((const float2*)g_S)[(size_t)w * 32 + l];
    float dot = a0 * sc.x + a1 * sc.y;
    #pragma unroll
    for (int d = 16; d >= 1; d >>= 1) dot += __shfl_xor_sync(0xffffffffu, dot, d);
    if (l == 0) scut[wl] = (double)dot;
    __syncthreads();
    if (threadIdx.x == 0) {
        double t = 0.0;
        #pragma unroll
        for (int q = 0; q < 8; q++) t += scut[q];
        atomicAdd(&g_cut, t);
    }
}

// ---------------------------------------------------------------- SS = S^T S  (4x4 register tiles)
__global__ void __launch_bounds__(256) k_SSmat() {
    __shared__ float4 srow[16][16];
    int t = threadIdx.x;
    int ti = t >> 4, tj = t & 15;
    float acc[4][4] = {};
    int chunk = (NN + gridDim.x - 1) / gridDim.x;
    int r0 = blockIdx.x * chunk;
    int r1 = min(r0 + chunk, NN);
    const float4* S4 = (const float4*)g_S;
    for (int rb = r0; rb < r1; rb += 16) {
        int nr = min(16, r1 - rb);
        if (t < nr * 16) srow[t >> 4][t & 15] = S4[(size_t)(rb + (t >> 4)) * 16 + (t & 15)];
        __syncthreads();
        for (int r = 0; r < nr; r++) {
            float4 a = srow[r][ti];
            float4 b = srow[r][tj];
            acc[0][0] += a.x * b.x; acc[0][1] += a.x * b.y; acc[0][2] += a.x * b.z; acc[0][3] += a.x * b.w;
            acc[1][0] += a.y * b.x; acc[1][1] += a.y * b.y; acc[1][2] += a.y * b.z; acc[1][3] += a.y * b.w;
            acc[2][0] += a.z * b.x; acc[2][1] += a.z * b.y; acc[2][2] += a.z * b.z; acc[2][3] += a.z * b.w;
            acc[3][0] += a.w * b.x; acc[3][1] += a.w * b.y; acc[3][2] += a.w * b.z; acc[3][3] += a.w * b.w;
        }
        __syncthreads();
    }
    #pragma unroll
    for (int p = 0; p < 4; p++)
        #pragma unroll
        for (int q = 0; q < 4; q++)
            atomicAdd(&g_SS[(ti * 4 + p) * KE + tj * 4 + q], acc[p][q]);
}

// ---------------------------------------------------------------- ortho + pump loss -> out[last]
__global__ void k_loss(float* __restrict__ out, int idx) {
    __shared__ double sh[256];
    __shared__ double dnrm;
    int t = threadIdx.x;
    double s = 0.0;
    for (int i = t; i < KE * KE; i += 256) { double v = (double)g_SS[i]; s += v * v; }
    sh[t] = s; __syncthreads();
    for (int off = 128; off >= 1; off >>= 1) { if (t < off) sh[t] += sh[t + off]; __syncthreads(); }
    if (t == 0) dnrm = sqrt(sh[0]);
    __syncthreads();
    double s2 = 0.0;
    for (int i = t; i < KE * KE; i += 256) {
        double v = (double)g_SS[i] / dnrm;
        if ((i >> 6) == (i & 63)) v -= 0.125;   // I / sqrt(64)
        s2 += v * v;
    }
    sh[t] = s2; __syncthreads();
    for (int off = 128; off >= 1; off >>= 1) { if (t < off) sh[t] += sh[t + off]; __syncthreads(); }
    if (t == 0) {
        double loss = -(g_cut / g_dt) + sqrt(sh[0]);
        out[idx] = (float)loss;
    }
}

// ---------------------------------------------------------------- final: logits + log_softmax
__global__ void __launch_bounds__(256) k_final(const float* __restrict__ x,
                                               const float* __restrict__ finW,
                                               float* __restrict__ out) {
    __shared__ float4 Wx[32][16];
    __shared__ float4 Wa[16][16];
    __shared__ float  bo[16];
    int t = threadIdx.x;
    for (int idx = t; idx < 512; idx += 256) {
        int c4 = idx >> 4, o = idx & 15;
        Wx[c4][o] = ((const float4*)g_Wc)[o * 32 + c4];
    }
    if (t < 256) {
        int k4 = t >> 4, o = t & 15;
        Wa[k4][o] = ((const float4*)finW)[o * 80 + 64 + k4];
    }
    if (t < 16) bo[t] = g_bc[t];
    __syncthreads();

    int n = blockIdx.x * 16 + (t >> 4);
    int o = t & 15;
    const float4* x4 = (const float4*)x;
    const float4* S4 = (const float4*)g_S;
    float acc = bo[o];
    #pragma unroll 8
    for (int c4 = 0; c4 < 32; c4++) {
        float4 xv = x4[(size_t)n * 32 + c4];
        float4 w = Wx[c4][o];
        acc += xv.x * w.x + xv.y * w.y + xv.z * w.z + xv.w * w.w;
    }
    #pragma unroll 8
    for (int k4 = 0; k4 < 16; k4++) {
        float4 sv = S4[(size_t)n * 16 + k4];
        float4 w = Wa[k4][o];
        acc += sv.x * w.x + sv.y * w.y + sv.z * w.z + sv.w * w.w;
    }
    float m = acc;
    #pragma unroll
    for (int d = 1; d < 16; d <<= 1) m = fmaxf(m, __shfl_xor_sync(0xffffffffu, m, d));
    float ex = expf(acc - m);
    float sum = ex;
    #pragma unroll
    for (int d = 1; d < 16; d <<= 1) sum += __shfl_xor_sync(0xffffffffu, sum, d);
    out[(size_t)n * 16 + o] = acc - m - logf(sum);
}

// ================================================================ launch
extern "C" void kernel_launch(void* const* d_in, const int* in_sizes, int n_in,
                              void* d_out, int out_size) {
    const float* x     = (const float*)d_in[0];
    const int*   ei    = (const int*)  d_in[1];
    const float* MLPW  = (const float*)d_in[2];
    const float* MLPb  = (const float*)d_in[3];
    const float* mlpxW = (const float*)d_in[4];
    const float* mlpxb = (const float*)d_in[5];
    const float* finW  = (const float*)d_in[6];
    const float* finb  = (const float*)d_in[7];
    float* out = (float*)d_out;

    const int* row = ei;
    const int* col = ei + EE;
    const int nblk_scan = (NN + 1023) / 1024;   // 98

    k_zero<<<(NN + 255) / 256, 256>>>();
    k_transpose<<<dim3(NN / 32, KE / 32), dim3(32, 8)>>>(MLPW);
    k_wcomb<<<8, 256>>>(finW, mlpxW, mlpxb, finb);
    k_hist<<<EE / 256, 256>>>(col);
    k_scan1<<<nblk_scan, 256>>>();
    k_scan2<<<1, 128>>>(nblk_scan);
    k_scan3<<<(NN + 255) / 256, 256>>>();
    k_scatter<<<EE / 256, 256>>>(row, col);
    k_spmm1<<<NN / 8, 256>>>(MLPb);
    k_spmm2<<<NN / 8, 256>>>();
    k_SSmat<<<592, 256>>>();
    k_loss<<<1, 256>>>(out, out_size - 1);
    k_final<<<NN / 16, 256>>>(x, finW, out);
}